// round 3
// baseline (speedup 1.0000x reference)
#include <cuda_runtime.h>
#include <cuda_bf16.h>
#include <cstdint>

// Problem constants (fixed by the dataset)
#define BATCH 16
#define TT    8192
#define HH    256
#define HQ    64
#define KSLOT 128
#define BS    64                 // token block size for partial sums
#define NBLK  (TT / BS)          // 128
#define NTILES (BATCH * NBLK)    // 2048
#define SROWA 260                // fp32 words per smem row (256 + 4 pad) -> conflict-free

// Scratch
__device__ float d_e[BATCH * TT];            // exp(score) per token
__device__ float d_S[BATCH * NBLK * HH];     // per-block sum of e*x
__device__ float d_E[BATCH * NBLK];          // per-block sum of e

__device__ __forceinline__ float tf32r(float x) {
    float r; asm("cvt.rna.tf32.f32 %0, %1;" : "=f"(r) : "f"(x)); return r;
}
__device__ __forceinline__ float tanha(float x) {
    float r; asm("tanh.approx.f32 %0, %1;" : "=f"(r) : "f"(x)); return r;
}

// smem: sX fp32[64][SROWA] | sE[64] | sP[64][8]
#define SMEM_A_BYTES ((64 * SROWA + 64 + 64 * 8) * 4)

__global__ void __launch_bounds__(256, 2) pass_a_kernel(
    const float* __restrict__ x,
    const float* __restrict__ W1,
    const float* __restrict__ b1,
    const float* __restrict__ W2,
    const float* __restrict__ b2)
{
    extern __shared__ float sm[];
    float* sX = sm;                       // 64*SROWA
    float* sE = sX + 64 * SROWA;          // 64
    float* sP = sE + 64;                  // 64*8 (token-major partials)

    const int tid  = threadIdx.x;
    const int warp = tid >> 5;            // 0..7, owns n-cols [warp*8, warp*8+8)
    const int lane = tid & 31;
    const int g    = lane >> 2;           // group id 0..7
    const int q    = lane & 3;            // id in group 0..3
    const int n0   = warp * 8;

    // Per-thread epilogue constants (cols c0, c1 of this thread's accumulators)
    const int c0 = n0 + q * 2;
    const float w2_0 = W2[c0],   w2_1 = W2[c0 + 1];
    const float b1_0 = b1[c0],   b1_1 = b1[c0 + 1];
    const float bb2  = b2[0];

    // Load W1 once into tf32 register B-fragments: Breg[kt][2], kt covers k=kt*8..kt*8+7
    uint32_t Breg[32][2];
    #pragma unroll
    for (int kt = 0; kt < 32; kt++) {
        const int k0 = kt * 8 + q;
        Breg[kt][0] = __float_as_uint(tf32r(W1[(k0)     * HQ + n0 + g]));
        Breg[kt][1] = __float_as_uint(tf32r(W1[(k0 + 4) * HQ + n0 + g]));
    }

    for (int tile = blockIdx.x; tile < NTILES; tile += gridDim.x) {
        const int b   = tile >> 7;        // NBLK = 128
        const int blk = tile & 127;
        const float* xblk = x + ((size_t)b * TT + (size_t)blk * BS) * HH;

        __syncthreads();                  // previous tile fully consumed

        // --- load x tile (float4), round to tf32 at store ---
        #pragma unroll
        for (int i = 0; i < 16; i++) {
            const int off = i * 1024 + tid * 4;
            float4 v = *(const float4*)(xblk + off);
            v.x = tf32r(v.x); v.y = tf32r(v.y); v.z = tf32r(v.z); v.w = tf32r(v.w);
            const int r = off >> 8, c = off & 255;
            *(float4*)&sX[r * SROWA + c] = v;
        }
        __syncthreads();

        // --- MMA: warp computes all 64 tokens x its 8 n-cols ---
        float acc[4][4];
        #pragma unroll
        for (int m = 0; m < 4; m++)
            #pragma unroll
            for (int i = 0; i < 4; i++) acc[m][i] = 0.f;

        #pragma unroll
        for (int kt = 0; kt < 32; kt++) {
            const int kb = kt * 8 + q;
            #pragma unroll
            for (int m = 0; m < 4; m++) {
                const int r = m * 16 + g;
                uint32_t a0 = __float_as_uint(sX[(r)     * SROWA + kb]);
                uint32_t a1 = __float_as_uint(sX[(r + 8) * SROWA + kb]);
                uint32_t a2 = __float_as_uint(sX[(r)     * SROWA + kb + 4]);
                uint32_t a3 = __float_as_uint(sX[(r + 8) * SROWA + kb + 4]);
                asm volatile(
                    "mma.sync.aligned.m16n8k8.row.col.f32.tf32.tf32.f32 "
                    "{%0,%1,%2,%3},{%4,%5,%6,%7},{%8,%9},{%0,%1,%2,%3};"
                    : "+f"(acc[m][0]), "+f"(acc[m][1]),
                      "+f"(acc[m][2]), "+f"(acc[m][3])
                    : "r"(a0), "r"(a1), "r"(a2), "r"(a3),
                      "r"(Breg[kt][0]), "r"(Breg[kt][1]));
            }
        }

        // --- epilogue: tanh + W2-dot -> per-warp partial score per token ---
        #pragma unroll
        for (int m = 0; m < 4; m++) {
            float p0 = tanha(acc[m][0] + b1_0) * w2_0 + tanha(acc[m][1] + b1_1) * w2_1;
            float p1 = tanha(acc[m][2] + b1_0) * w2_0 + tanha(acc[m][3] + b1_1) * w2_1;
            p0 += __shfl_xor_sync(0xffffffffu, p0, 1);
            p0 += __shfl_xor_sync(0xffffffffu, p0, 2);
            p1 += __shfl_xor_sync(0xffffffffu, p1, 1);
            p1 += __shfl_xor_sync(0xffffffffu, p1, 2);
            if (q == 0) {
                sP[(m * 16 + g)     * 8 + warp] = p0;
                sP[(m * 16 + g + 8) * 8 + warp] = p1;
            }
        }
        __syncthreads();

        // --- reduce 8 warps, exp, publish e ---
        if (tid < 64) {
            float s = bb2;
            #pragma unroll
            for (int w = 0; w < 8; w++) s += sP[tid * 8 + w];
            const float e = __expf(s);
            sE[tid] = e;
            d_e[b * TT + blk * BS + tid] = e;
        }
        __syncthreads();

        // --- block partial sums from smem (fp32, tf32-rounded x) ---
        float a = 0.f, den = 0.f;
        #pragma unroll 8
        for (int t = 0; t < BS; t++) {
            const float e = sE[t];
            a   += e * sX[t * SROWA + tid];
            den += e;
        }
        d_S[((size_t)b * NBLK + blk) * HH + tid] = a;
        if (tid == 0) d_E[b * NBLK + blk] = den;
    }
}

__global__ void __launch_bounds__(256) pass_b_kernel(
    const float* __restrict__ x,
    const int*   __restrict__ boundaries,
    const int*   __restrict__ slot_mask,
    float*       __restrict__ out)
{
    const int k   = blockIdx.x;       // 0..KSLOT-1
    const int b   = blockIdx.y;       // 0..BATCH-1
    const int tid = threadIdx.x;      // == h index

    const int sidx  = b * KSLOT + k;
    const int start = boundaries[sidx * 2];
    const int end   = boundaries[sidx * 2 + 1];
    const int mask  = slot_mask[sidx];

    float* o = out + (size_t)sidx * HH;
    if (mask <= 0 || start >= end) { o[tid] = 0.f; return; }

    const float* xb = x + (size_t)b * TT * HH;
    const float* eb = d_e + b * TT;
    const float* Sb = d_S + (size_t)b * NBLK * HH;
    const float* Eb = d_E + b * NBLK;

    float acc = 0.f, den = 0.f;

    const int fb = (start + BS - 1) / BS;  // first full block
    const int lb = end / BS;               // one past last full block

    if (fb < lb) {
        // full blocks, 4-wide unroll with independent chains
        float a0 = 0.f, a1 = 0.f, a2 = 0.f, a3 = 0.f;
        float d0 = 0.f, d1 = 0.f, d2 = 0.f, d3 = 0.f;
        int i = fb;
        for (; i + 4 <= lb; i += 4) {
            a0 += Sb[(size_t)(i + 0) * HH + tid]; d0 += Eb[i + 0];
            a1 += Sb[(size_t)(i + 1) * HH + tid]; d1 += Eb[i + 1];
            a2 += Sb[(size_t)(i + 2) * HH + tid]; d2 += Eb[i + 2];
            a3 += Sb[(size_t)(i + 3) * HH + tid]; d3 += Eb[i + 3];
        }
        for (; i < lb; i++) { a0 += Sb[(size_t)i * HH + tid]; d0 += Eb[i]; }
        acc = (a0 + a1) + (a2 + a3);
        den = (d0 + d1) + (d2 + d3);

        // left edge [start, fb*BS)
        {
            const int le = fb * BS;
            float ea = 0.f, eb2 = 0.f, da = 0.f, db = 0.f;
            int t = start;
            for (; t + 2 <= le; t += 2) {
                const float e0 = eb[t], e1 = eb[t + 1];
                ea  += e0 * xb[(size_t)(t)     * HH + tid]; da += e0;
                eb2 += e1 * xb[(size_t)(t + 1) * HH + tid]; db += e1;
            }
            for (; t < le; t++) { const float e = eb[t]; ea += e * xb[(size_t)t * HH + tid]; da += e; }
            acc += ea + eb2; den += da + db;
        }
        // right edge [lb*BS, end)
        {
            const int rs = lb * BS;
            float ea = 0.f, eb2 = 0.f, da = 0.f, db = 0.f;
            int t = rs;
            for (; t + 2 <= end; t += 2) {
                const float e0 = eb[t], e1 = eb[t + 1];
                ea  += e0 * xb[(size_t)(t)     * HH + tid]; da += e0;
                eb2 += e1 * xb[(size_t)(t + 1) * HH + tid]; db += e1;
            }
            for (; t < end; t++) { const float e = eb[t]; ea += e * xb[(size_t)t * HH + tid]; da += e; }
            acc += ea + eb2; den += da + db;
        }
    } else {
        // short slot entirely inside one block
        float ea = 0.f, eb2 = 0.f, da = 0.f, db = 0.f;
        int t = start;
        for (; t + 2 <= end; t += 2) {
            const float e0 = eb[t], e1 = eb[t + 1];
            ea  += e0 * xb[(size_t)(t)     * HH + tid]; da += e0;
            eb2 += e1 * xb[(size_t)(t + 1) * HH + tid]; db += e1;
        }
        for (; t < end; t++) { const float e = eb[t]; ea += e * xb[(size_t)t * HH + tid]; da += e; }
        acc = ea + eb2; den = da + db;
    }

    o[tid] = acc / den;  // den > 0 guaranteed: end > start and e_t > 0
}

extern "C" void kernel_launch(void* const* d_in, const int* in_sizes, int n_in,
                              void* d_out, int out_size)
{
    const float* x          = (const float*)d_in[0];
    const int*   boundaries = (const int*)d_in[1];
    const int*   slot_mask  = (const int*)d_in[2];
    const float* W1         = (const float*)d_in[3];
    const float* b1         = (const float*)d_in[4];
    const float* W2         = (const float*)d_in[5];
    const float* b2         = (const float*)d_in[6];
    float* out = (float*)d_out;

    cudaFuncSetAttribute(pass_a_kernel,
                         cudaFuncAttributeMaxDynamicSharedMemorySize,
                         SMEM_A_BYTES);

    pass_a_kernel<<<296, 256, SMEM_A_BYTES>>>(x, W1, b1, W2, b2);
    pass_b_kernel<<<dim3(KSLOT, BATCH), 256>>>(x, boundaries, slot_mask, out);
}

// round 4
// speedup vs baseline: 1.2372x; 1.2372x over previous
#include <cuda_runtime.h>
#include <cuda_bf16.h>
#include <cstdint>

// Problem constants
#define BATCH 16
#define TT    8192
#define HH    256
#define HQ    64
#define KSLOT 128
#define NTILES (BATCH * (TT / 64))      // 2048 tiles of 64 tokens
#define NB1   (TT / 16)                 // 512 fine blocks (16 tokens)
#define NSB   (TT / 256)                // 32 superblocks (256 tokens)
#define SROWA 260                       // fp32 words per smem row (pad 4)
#define XT_WORDS (64 * SROWA)

// Scratch
__device__ float d_e [BATCH * TT];            // exp(score) per token
__device__ float d_S [BATCH * NB1 * HH];      // 16-token block sums of e*x
__device__ float d_E [BATCH * NB1];           // 16-token block sums of e
__device__ float d_S2[BATCH * NSB * HH];      // 256-token superblock sums
__device__ float d_E2[BATCH * NSB];

__device__ __forceinline__ float tf32r(float x) {
    float r; asm("cvt.rna.tf32.f32 %0, %1;" : "=f"(r) : "f"(x)); return r;
}
__device__ __forceinline__ float tanha(float x) {
    float r; asm("tanh.approx.f32 %0, %1;" : "=f"(r) : "f"(x)); return r;
}
__device__ __forceinline__ void cpa16(uint32_t dst, const float* src) {
    asm volatile("cp.async.cg.shared.global [%0], [%1], 16;" :: "r"(dst), "l"(src));
}

// smem: sX[2][64][SROWA] | sE[64] | sP[64][4]
#define SMEM_A_BYTES ((2 * XT_WORDS + 64 + 64 * 4) * 4)

__global__ void __launch_bounds__(256, 1) pass_a_kernel(
    const float* __restrict__ x,
    const float* __restrict__ W1,
    const float* __restrict__ b1,
    const float* __restrict__ W2,
    const float* __restrict__ b2)
{
    extern __shared__ float sm[];
    float* sXbuf[2] = { sm, sm + XT_WORDS };
    float* sE = sm + 2 * XT_WORDS;
    float* sP = sE + 64;

    const int tid  = threadIdx.x;
    const int warp = tid >> 5;
    const int lane = tid & 31;
    const int g    = lane >> 2;          // 0..7
    const int q    = lane & 3;           // 0..3
    const int half = warp >> 2;          // token half: 0 -> rows 0..31, 1 -> 32..63
    const int nq   = warp & 3;           // n quarter: cols [nq*16, nq*16+16)

    uint32_t smem_u32;
    { uint64_t t64; asm("cvta.to.shared.u64 %0, %1;" : "=l"(t64) : "l"(sm));
      smem_u32 = (uint32_t)t64; }

    // --- W1 register-resident B fragments: Breg[kt][nt][2] ---
    uint32_t Breg[32][2][2];
    #pragma unroll
    for (int kt = 0; kt < 32; kt++)
        #pragma unroll
        for (int nt = 0; nt < 2; nt++) {
            const int n = nq * 16 + nt * 8 + g;
            Breg[kt][nt][0] = __float_as_uint(tf32r(W1[(kt * 8 + q)     * HQ + n]));
            Breg[kt][nt][1] = __float_as_uint(tf32r(W1[(kt * 8 + q + 4) * HQ + n]));
        }

    // Epilogue constants: this thread's 4 accumulator columns
    float w2c[2][2], b1c[2][2];
    #pragma unroll
    for (int nt = 0; nt < 2; nt++)
        #pragma unroll
        for (int j = 0; j < 2; j++) {
            const int c = nq * 16 + nt * 8 + 2 * q + j;
            w2c[nt][j] = W2[c]; b1c[nt][j] = b1[c];
        }
    const float bb2 = b2[0];

    // Per-thread cp.async source/dst offsets (16 chunks of 16B per tile)
    // words offset: i*1024 + tid*4 ; dst row = off>>8, col = off&255
    int tile = blockIdx.x;
    {   // prefetch first tile into buf 0
        const float* src = x + (size_t)tile * (64 * HH);
        #pragma unroll
        for (int i = 0; i < 16; i++) {
            const int off = i * 1024 + tid * 4;
            const int r = off >> 8, c = off & 255;
            cpa16(smem_u32 + (uint32_t)(r * SROWA + c) * 4, src + off);
        }
        asm volatile("cp.async.commit_group;");
    }

    int buf = 0;
    for (; tile < NTILES; tile += gridDim.x, buf ^= 1) {
        float* sX  = sXbuf[buf];
        const int next = tile + gridDim.x;

        __syncthreads();   // prior compute finished -> safe to refill other buf

        if (next < NTILES) {
            const float* src = x + (size_t)next * (64 * HH);
            const uint32_t base = smem_u32 + (uint32_t)((buf ^ 1) * XT_WORDS) * 4;
            #pragma unroll
            for (int i = 0; i < 16; i++) {
                const int off = i * 1024 + tid * 4;
                const int r = off >> 8, c = off & 255;
                cpa16(base + (uint32_t)(r * SROWA + c) * 4, src + off);
            }
            asm volatile("cp.async.commit_group;");
            asm volatile("cp.async.wait_group 1;");
        } else {
            asm volatile("cp.async.wait_group 0;");
        }
        __syncthreads();   // current buffer visible to all threads

        // --- MMA: warp computes its 32 tokens x its 16 n-cols ---
        float acc[2][2][4];
        #pragma unroll
        for (int m = 0; m < 2; m++)
            #pragma unroll
            for (int nt = 0; nt < 2; nt++)
                #pragma unroll
                for (int i = 0; i < 4; i++) acc[m][nt][i] = 0.f;

        const int r0 = half * 32;
        #pragma unroll
        for (int kt = 0; kt < 32; kt++) {
            const int kb = kt * 8 + q;
            #pragma unroll
            for (int m = 0; m < 2; m++) {
                const int rr = r0 + m * 16 + g;
                uint32_t a0 = __float_as_uint(sX[(rr)     * SROWA + kb]);
                uint32_t a1 = __float_as_uint(sX[(rr + 8) * SROWA + kb]);
                uint32_t a2 = __float_as_uint(sX[(rr)     * SROWA + kb + 4]);
                uint32_t a3 = __float_as_uint(sX[(rr + 8) * SROWA + kb + 4]);
                #pragma unroll
                for (int nt = 0; nt < 2; nt++) {
                    asm volatile(
                        "mma.sync.aligned.m16n8k8.row.col.f32.tf32.tf32.f32 "
                        "{%0,%1,%2,%3},{%4,%5,%6,%7},{%8,%9},{%0,%1,%2,%3};"
                        : "+f"(acc[m][nt][0]), "+f"(acc[m][nt][1]),
                          "+f"(acc[m][nt][2]), "+f"(acc[m][nt][3])
                        : "r"(a0), "r"(a1), "r"(a2), "r"(a3),
                          "r"(Breg[kt][nt][0]), "r"(Breg[kt][nt][1]));
                }
            }
        }

        // --- epilogue: tanh + W2-dot -> per-warp partial per token ---
        #pragma unroll
        for (int m = 0; m < 2; m++) {
            const int rr = r0 + m * 16 + g;
            float p0 = 0.f, p1 = 0.f;
            #pragma unroll
            for (int nt = 0; nt < 2; nt++) {
                p0 += tanha(acc[m][nt][0] + b1c[nt][0]) * w2c[nt][0]
                    + tanha(acc[m][nt][1] + b1c[nt][1]) * w2c[nt][1];
                p1 += tanha(acc[m][nt][2] + b1c[nt][0]) * w2c[nt][0]
                    + tanha(acc[m][nt][3] + b1c[nt][1]) * w2c[nt][1];
            }
            p0 += __shfl_xor_sync(0xffffffffu, p0, 1);
            p0 += __shfl_xor_sync(0xffffffffu, p0, 2);
            p1 += __shfl_xor_sync(0xffffffffu, p1, 1);
            p1 += __shfl_xor_sync(0xffffffffu, p1, 2);
            if (q == 0) {
                sP[(rr)     * 4 + nq] = p0;
                sP[(rr + 8) * 4 + nq] = p1;
            }
        }
        __syncthreads();

        const int b     = tile >> 7;         // batch
        const int blk64 = tile & 127;        // 64-token tile within batch

        if (tid < 64) {
            float s = bb2 + sP[tid * 4] + sP[tid * 4 + 1]
                          + sP[tid * 4 + 2] + sP[tid * 4 + 3];
            const float e = __expf(s);
            sE[tid] = e;
            d_e[b * TT + blk64 * 64 + tid] = e;
        }
        __syncthreads();

        // --- four 16-token block partial sums (full fp32 x) ---
        #pragma unroll
        for (int j = 0; j < 4; j++) {
            float a = 0.f, den = 0.f;
            #pragma unroll
            for (int t = j * 16; t < j * 16 + 16; t++) {
                const float e = sE[t];
                a   += e * sX[t * SROWA + tid];
                den += e;
            }
            const int bi = b * NB1 + blk64 * 4 + j;
            d_S[(size_t)bi * HH + tid] = a;
            if (tid == 0) d_E[bi] = den;
        }
    }
}

// Aggregate 16 fine blocks -> 1 superblock
__global__ void __launch_bounds__(256) pass_ab_kernel()
{
    const int sb  = blockIdx.x & (NSB - 1);
    const int b   = blockIdx.x >> 5;
    const int tid = threadIdx.x;

    const float* Sb = d_S + ((size_t)(b * NB1 + sb * 16)) * HH + tid;
    float s0 = 0.f, s1 = 0.f, s2 = 0.f, s3 = 0.f;
    #pragma unroll
    for (int i = 0; i < 16; i += 4) {
        s0 += Sb[(size_t)(i + 0) * HH];
        s1 += Sb[(size_t)(i + 1) * HH];
        s2 += Sb[(size_t)(i + 2) * HH];
        s3 += Sb[(size_t)(i + 3) * HH];
    }
    d_S2[(size_t)(b * NSB + sb) * HH + tid] = (s0 + s1) + (s2 + s3);
    if (tid == 0) {
        float e = 0.f;
        #pragma unroll
        for (int i = 0; i < 16; i++) e += d_E[b * NB1 + sb * 16 + i];
        d_E2[b * NSB + sb] = e;
    }
}

__global__ void __launch_bounds__(256) pass_b_kernel(
    const float* __restrict__ x,
    const int*   __restrict__ boundaries,
    const int*   __restrict__ slot_mask,
    float*       __restrict__ out)
{
    const int k   = blockIdx.x;
    const int b   = blockIdx.y;
    const int tid = threadIdx.x;     // h index

    const int sidx  = b * KSLOT + k;
    const int start = boundaries[sidx * 2];
    const int end   = boundaries[sidx * 2 + 1];
    const int mask  = slot_mask[sidx];

    float* o = out + (size_t)sidx * HH;
    if (mask <= 0 || start >= end) { o[tid] = 0.f; return; }

    const float* xb  = x    + (size_t)b * TT * HH;
    const float* eb  = d_e  + b * TT;
    const float* Sb1 = d_S  + (size_t)b * NB1 * HH;
    const float* Eb1 = d_E  + b * NB1;
    const float* Sb2 = d_S2 + (size_t)b * NSB * HH;
    const float* Eb2 = d_E2 + b * NSB;

    float acc = 0.f, den = 0.f;

    // token range helper (2 independent chains)
    auto tokens = [&](int t0, int t1) {
        float ea = 0.f, ec = 0.f, da = 0.f, dc = 0.f;
        int t = t0;
        for (; t + 2 <= t1; t += 2) {
            const float e0 = eb[t], e1 = eb[t + 1];
            ea += e0 * xb[(size_t)(t)     * HH + tid]; da += e0;
            ec += e1 * xb[(size_t)(t + 1) * HH + tid]; dc += e1;
        }
        if (t < t1) { const float e = eb[t]; ea += e * xb[(size_t)t * HH + tid]; da += e; }
        acc += ea + ec; den += da + dc;
    };
    // fine-block range [i0, i1) in 16-token units
    auto blocks = [&](int i0, int i1) {
        float a0 = 0.f, a1 = 0.f, d0 = 0.f, d1 = 0.f;
        int i = i0;
        for (; i + 2 <= i1; i += 2) {
            a0 += Sb1[(size_t)(i)     * HH + tid]; d0 += Eb1[i];
            a1 += Sb1[(size_t)(i + 1) * HH + tid]; d1 += Eb1[i + 1];
        }
        if (i < i1) { a0 += Sb1[(size_t)i * HH + tid]; d0 += Eb1[i]; }
        acc += a0 + a1; den += d0 + d1;
    };

    const int fb = (start + 15) >> 4;    // first full fine block
    const int lb = end >> 4;             // one past last full fine block

    if (fb >= lb) {
        tokens(start, end);
    } else {
        tokens(start, fb * 16);
        tokens(lb * 16, end);

        const int fs = (fb + 15) >> 4;   // first full superblock (in SB units)
        const int ls = lb >> 4;
        if (fs >= ls) {
            blocks(fb, lb);
        } else {
            blocks(fb, fs * 16);
            blocks(ls * 16, lb);
            // superblocks [fs, ls), 4 chains
            float a0 = 0.f, a1 = 0.f, a2 = 0.f, a3 = 0.f;
            float d0 = 0.f, d1 = 0.f, d2 = 0.f, d3 = 0.f;
            int i = fs;
            for (; i + 4 <= ls; i += 4) {
                a0 += Sb2[(size_t)(i + 0) * HH + tid]; d0 += Eb2[i + 0];
                a1 += Sb2[(size_t)(i + 1) * HH + tid]; d1 += Eb2[i + 1];
                a2 += Sb2[(size_t)(i + 2) * HH + tid]; d2 += Eb2[i + 2];
                a3 += Sb2[(size_t)(i + 3) * HH + tid]; d3 += Eb2[i + 3];
            }
            for (; i < ls; i++) { a0 += Sb2[(size_t)i * HH + tid]; d0 += Eb2[i]; }
            acc += (a0 + a1) + (a2 + a3);
            den += (d0 + d1) + (d2 + d3);
        }
    }

    o[tid] = acc / den;   // den > 0: end > start and all e_t > 0
}

extern "C" void kernel_launch(void* const* d_in, const int* in_sizes, int n_in,
                              void* d_out, int out_size)
{
    const float* x          = (const float*)d_in[0];
    const int*   boundaries = (const int*)d_in[1];
    const int*   slot_mask  = (const int*)d_in[2];
    const float* W1         = (const float*)d_in[3];
    const float* b1         = (const float*)d_in[4];
    const float* W2         = (const float*)d_in[5];
    const float* b2         = (const float*)d_in[6];
    float* out = (float*)d_out;

    cudaFuncSetAttribute(pass_a_kernel,
                         cudaFuncAttributeMaxDynamicSharedMemorySize,
                         SMEM_A_BYTES);

    pass_a_kernel<<<148, 256, SMEM_A_BYTES>>>(x, W1, b1, W2, b2);
    pass_ab_kernel<<<BATCH * NSB, 256>>>();
    pass_b_kernel<<<dim3(KSLOT, BATCH), 256>>>(x, boundaries, slot_mask, out);
}